// round 2
// baseline (speedup 1.0000x reference)
#include <cuda_runtime.h>
#include <math.h>

#define NB 2
#define NS 2048
#define NE 1024
#define NH 16
#define ND 64
#define NT 32            // NS / 64 key tiles
#define NEGV (-1e9f)
#define QSCALE 0.125f    // 1/sqrt(64)

// Scratch (allocation-free rule: __device__ globals)
__device__ float g_q[NB*NH*NS*ND];
__device__ float g_k[NB*NH*NS*ND];
__device__ float g_v[NB*NH*NS*ND];
__device__ float g_suf[NB*NH*(NT+1)*ND];   // tile-granular suffix sums of V

// ---------------------------------------------------------------------------
// Kernel 1: fused Q/K/V projections.  out[m,n] = X[m,:] . W[n,:] + b[n]
// M = B*S = 4096, N = K = 1024.  64x64 tile, BK=16, 256 threads, 4x4 micro.
// Output written directly in [B,H,S,D] layout.
// ---------------------------------------------------------------------------
__global__ __launch_bounds__(256) void proj_kernel(
    const float* __restrict__ xq, const float* __restrict__ xk, const float* __restrict__ xv,
    const float* __restrict__ wq, const float* __restrict__ wk, const float* __restrict__ wv,
    const float* __restrict__ bq, const float* __restrict__ bk, const float* __restrict__ bv)
{
    __shared__ float Xs[16][68];
    __shared__ float Ws[16][68];

    const int z = blockIdx.z;
    const float* X    = (z == 0) ? xq : (z == 1) ? xk : xv;
    const float* W    = (z == 0) ? wq : (z == 1) ? wk : wv;
    const float* bias = (z == 0) ? bq : (z == 1) ? bk : bv;
    float* out        = (z == 0) ? g_q : (z == 1) ? g_k : g_v;

    const int m0 = blockIdx.y * 64;
    const int n0 = blockIdx.x * 64;
    const int tid = threadIdx.x;
    const int tx = tid & 15, ty = tid >> 4;
    const int lr = tid >> 2;           // 0..63  (row within tile)
    const int lc = (tid & 3) << 2;     // 0,4,8,12  (16-wide k slice)

    float acc[4][4] = {};

    for (int k0 = 0; k0 < NE; k0 += 16) {
        float4 xr = *(const float4*)(X + (size_t)(m0 + lr) * NE + k0 + lc);
        float4 wr = *(const float4*)(W + (size_t)(n0 + lr) * NE + k0 + lc);
        __syncthreads();
        Xs[lc+0][lr] = xr.x; Xs[lc+1][lr] = xr.y; Xs[lc+2][lr] = xr.z; Xs[lc+3][lr] = xr.w;
        Ws[lc+0][lr] = wr.x; Ws[lc+1][lr] = wr.y; Ws[lc+2][lr] = wr.z; Ws[lc+3][lr] = wr.w;
        __syncthreads();
        #pragma unroll
        for (int kk = 0; kk < 16; kk++) {
            float4 a4 = *(const float4*)&Xs[kk][ty * 4];
            float4 b4 = *(const float4*)&Ws[kk][tx * 4];
            float av[4] = {a4.x, a4.y, a4.z, a4.w};
            float bw[4] = {b4.x, b4.y, b4.z, b4.w};
            #pragma unroll
            for (int i = 0; i < 4; i++)
                #pragma unroll
                for (int j = 0; j < 4; j++)
                    acc[i][j] += av[i] * bw[j];
        }
    }

    const int bb = m0 >> 11;          // batch (tiles never straddle the batch edge)
    const int s0 = m0 & (NS - 1);
    const int h  = n0 >> 6;           // head (n-tile == one head, ND = 64)
    float4 bv4 = *(const float4*)(bias + n0 + tx * 4);
    #pragma unroll
    for (int i = 0; i < 4; i++) {
        int s = s0 + ty * 4 + i;
        float4 o;
        o.x = acc[i][0] + bv4.x; o.y = acc[i][1] + bv4.y;
        o.z = acc[i][2] + bv4.z; o.w = acc[i][3] + bv4.w;
        *(float4*)(out + ((size_t)(bb * NH + h) * NS + s) * ND + tx * 4) = o;
    }
}

// ---------------------------------------------------------------------------
// Kernel 2: per-(b,h) tile-granular suffix sums of V over the sequence dim.
// g_suf[bh][t][d] = sum_{s >= 64*t} v[s][d];  g_suf[bh][NT][d] = 0.
// ---------------------------------------------------------------------------
__global__ void suffix_kernel()
{
    const int bh = blockIdx.x;           // 0..31
    const int d  = threadIdx.x;          // 0..63
    const float* v = g_v + (size_t)bh * NS * ND;
    float* suf = g_suf + (size_t)bh * (NT + 1) * ND;
    float acc = 0.f;
    suf[NT * ND + d] = 0.f;
    for (int t = NT - 1; t >= 0; t--) {
        for (int s = t * 64 + 63; s >= t * 64; s--) acc += v[(size_t)s * ND + d];
        suf[t * ND + d] = acc;
    }
}

// ---------------------------------------------------------------------------
// Kernel 3: attention.  One block = (b, h, 64-row q-tile).
//   out[q,d] = sum_{k in tiles<=tq} s[q,k]*v[k,d] + NEG*suffixV[d] - lse[q]*totalV[d]
// s includes bias and NEG for masked entries inside the diagonal tile;
// fully-masked k-tiles fold into the suffix term (causal halving).
// lse computed online (linear log-softmax => no flash rescaling of A).
// ---------------------------------------------------------------------------
__global__ __launch_bounds__(256) void attn_kernel(
    const float* __restrict__ pos_bias, float* __restrict__ out)
{
    extern __shared__ float sm[];
    float* Qt    = sm;                   // [64 d][68]  Q^T, pre-scaled
    float* Kt    = Qt + 64 * 68;         // [64 d][68]  K^T
    float* St    = Kt + 64 * 68;         // [64 k][68]  S^T (k-major, q contiguous)
    float* Vs    = St + 64 * 68;         // [64 k][64]  V natural
    float* posr  = Vs + 64 * 64;         // 4096 (full pos_bias row for this head)
    float* row_m = posr + 4096;          // 64
    float* row_l = row_m + 64;           // 64
    float* lse_s = row_l + 64;           // 64

    const int tq = blockIdx.x;
    const int h  = blockIdx.y;
    const int b  = blockIdx.z;
    const int q0 = tq * 64;
    const int tid = threadIdx.x;
    const int tx = tid & 15, ty = tid >> 4;
    const int row  = tid & 63;           // 0..63 tile row for 64x64 loads
    const int dgrp = (tid >> 6) * 16;    // 0,16,32,48 column group base

    const size_t base = (size_t)(b * NH + h) * NS * ND;

    // ---- load full 64x64 Q tile transposed, pre-scaled (4 float4 per thread) ----
    #pragma unroll
    for (int i = 0; i < 4; i++) {
        const int d = dgrp + i * 4;
        float4 qv = *(const float4*)(g_q + base + (size_t)(q0 + row) * ND + d);
        Qt[(d+0)*68 + row] = qv.x * QSCALE;
        Qt[(d+1)*68 + row] = qv.y * QSCALE;
        Qt[(d+2)*68 + row] = qv.z * QSCALE;
        Qt[(d+3)*68 + row] = qv.w * QSCALE;
    }
    for (int i = tid; i < 2 * NS - 1; i += 256)
        posr[i] = pos_bias[(size_t)h * (2 * NS - 1) + i];
    if (tid < 64) { row_m[tid] = -1e30f; row_l[tid] = 0.f; }
    __syncthreads();

    float A[4][4] = {};

    for (int t = 0; t <= tq; t++) {
        const int k0 = t * 64;
        float4 kv[4], vv[4];
        #pragma unroll
        for (int i = 0; i < 4; i++) {
            const int d = dgrp + i * 4;
            kv[i] = *(const float4*)(g_k + base + (size_t)(k0 + row) * ND + d);
            vv[i] = *(const float4*)(g_v + base + (size_t)(k0 + row) * ND + d);
        }
        __syncthreads();                 // previous iteration fully consumed
        #pragma unroll
        for (int i = 0; i < 4; i++) {
            const int d = dgrp + i * 4;
            Kt[(d+0)*68 + row] = kv[i].x; Kt[(d+1)*68 + row] = kv[i].y;
            Kt[(d+2)*68 + row] = kv[i].z; Kt[(d+3)*68 + row] = kv[i].w;
            *(float4*)(Vs + row * 64 + d) = vv[i];
        }
        __syncthreads();

        // ---- S = Qs . K^T ----
        float c[4][4] = {};
        #pragma unroll 8
        for (int kk = 0; kk < 64; kk++) {
            float4 a4 = *(const float4*)(Qt + kk * 68 + ty * 4);
            float4 b4 = *(const float4*)(Kt + kk * 68 + tx * 4);
            float av[4] = {a4.x, a4.y, a4.z, a4.w};
            float bw[4] = {b4.x, b4.y, b4.z, b4.w};
            #pragma unroll
            for (int i = 0; i < 4; i++)
                #pragma unroll
                for (int j = 0; j < 4; j++)
                    c[i][j] += av[i] * bw[j];
        }
        // bias + mask, store S^T
        #pragma unroll
        for (int i = 0; i < 4; i++) {
            const int q = q0 + ty * 4 + i;
            #pragma unroll
            for (int j = 0; j < 4; j++) {
                const int k = k0 + tx * 4 + j;
                float val = c[i][j] + posr[q - k + NS - 1];
                if (k > q) val = NEGV;
                St[(tx * 4 + j) * 68 + (ty * 4 + i)] = val;
            }
        }
        __syncthreads();

        // ---- online logsumexp (warps 0-1) ----
        if (tid < 64) {
            float mo = row_m[tid];
            float mt = mo;
            #pragma unroll 8
            for (int j = 0; j < 64; j++) mt = fmaxf(mt, St[j * 68 + tid]);
            float l = row_l[tid] * __expf(mo - mt);
            #pragma unroll 8
            for (int j = 0; j < 64; j++) l += __expf(St[j * 68 + tid] - mt);
            row_m[tid] = mt; row_l[tid] = l;
        }

        // ---- A += S . V  (raw s, incl. NEG in the diagonal tile) ----
        #pragma unroll 8
        for (int j = 0; j < 64; j++) {
            float4 a4 = *(const float4*)(St + j * 68 + ty * 4);
            float4 v4 = *(const float4*)(Vs + j * 64 + tx * 4);
            float av[4] = {a4.x, a4.y, a4.z, a4.w};
            #pragma unroll
            for (int i = 0; i < 4; i++) {
                A[i][0] += av[i] * v4.x; A[i][1] += av[i] * v4.y;
                A[i][2] += av[i] * v4.z; A[i][3] += av[i] * v4.w;
            }
        }
    }

    __syncthreads();
    if (tid < 64) lse_s[tid] = row_m[tid] + logf(row_l[tid]);
    __syncthreads();

    const float* suf = g_suf + (size_t)(b * NH + h) * (NT + 1) * ND;
    float4 vt = *(const float4*)(suf + tx * 4);                         // total V sum
    float4 vl = *(const float4*)(suf + (size_t)(tq + 1) * ND + tx * 4); // fully-masked tail

    #pragma unroll
    for (int i = 0; i < 4; i++) {
        const int q = q0 + ty * 4 + i;
        const float lse = lse_s[ty * 4 + i];
        float4 o;
        o.x = A[i][0] + NEGV * vl.x - lse * vt.x;
        o.y = A[i][1] + NEGV * vl.y - lse * vt.y;
        o.z = A[i][2] + NEGV * vl.z - lse * vt.z;
        o.w = A[i][3] + NEGV * vl.w - lse * vt.w;
        *(float4*)(out + ((size_t)(b * NS + q)) * NE + h * ND + tx * 4) = o;
    }
}

// ---------------------------------------------------------------------------
extern "C" void kernel_launch(void* const* d_in, const int* in_sizes, int n_in,
                              void* d_out, int out_size)
{
    (void)in_sizes; (void)n_in; (void)out_size;
    const float* query = (const float*)d_in[0];
    const float* key_  = (const float*)d_in[1];
    const float* value = (const float*)d_in[2];
    const float* Wq    = (const float*)d_in[3];
    const float* bq    = (const float*)d_in[4];
    const float* Wk    = (const float*)d_in[5];
    const float* bk    = (const float*)d_in[6];
    const float* Wv    = (const float*)d_in[7];
    const float* bv    = (const float*)d_in[8];
    const float* pos   = (const float*)d_in[9];
    // d_in[10..12] (idx0, idx1, mask) are implicit in the kernel math.

    proj_kernel<<<dim3(16, 64, 3), 256>>>(query, key_, value, Wq, Wk, Wv, bq, bk, bv);
    suffix_kernel<<<dim3(NB * NH), 64>>>();

    const int SMEM = (3 * 64 * 68 + 64 * 64 + 4096 + 192) * 4;  // 85760 B
    cudaFuncSetAttribute(attn_kernel, cudaFuncAttributeMaxDynamicSharedMemorySize, SMEM);
    attn_kernel<<<dim3(NT, NH, NB), 256, SMEM>>>(pos, (float*)d_out);
}

// round 5
// speedup vs baseline: 1.4757x; 1.4757x over previous
#include <cuda_runtime.h>
#include <cuda_bf16.h>
#include <math.h>
#include <stdint.h>

#define NB 2
#define NS 2048
#define NE 1024
#define NH 16
#define ND 64
#define NT 32            // NS / 64 key tiles
#define NEGV (-1e9f)
#define QSCALE 0.125f    // 1/sqrt(64)

// Scratch (allocation-free rule: __device__ globals)
__device__ float g_q[NB*NH*NS*ND];
__device__ float g_k[NB*NH*NS*ND];
__device__ float g_v[NB*NH*NS*ND];
__device__ float g_suf[NB*NH*(NT+1)*ND];        // tile-granular suffix sums of V
// bf16 slices: x: 0=query 1=key 2=value_hi 3=value_lo ; w: 0=Wq 1=Wk 2=Wv_hi 3=Wv_lo
__device__ __nv_bfloat16 g_xb[4u*4096*1024];
__device__ __nv_bfloat16 g_wb[4u*1024*1024];

// ---------------------------------------------------------------------------
// warp-level bf16 MMA helper (portable HMMA, works on plain sm_103 target)
// ---------------------------------------------------------------------------
__device__ __forceinline__ void mma16816(float* c, const uint32_t* a, const uint32_t* b) {
    asm volatile("mma.sync.aligned.m16n8k16.row.col.f32.bf16.bf16.f32 "
        "{%0,%1,%2,%3}, {%4,%5,%6,%7}, {%8,%9}, {%0,%1,%2,%3};"
        : "+f"(c[0]), "+f"(c[1]), "+f"(c[2]), "+f"(c[3])
        : "r"(a[0]), "r"(a[1]), "r"(a[2]), "r"(a[3]), "r"(b[0]), "r"(b[1]));
}

// ---------------------------------------------------------------------------
// Kernel 0: fp32 -> bf16 (hi), optionally also residual (lo) into the next slice.
// which: 0..3 selects g_xb slice, 4..7 selects g_wb slice. loOff = slice stride.
// ---------------------------------------------------------------------------
__global__ void f2bf_kernel(const float4* __restrict__ src, int which, int split, int n4)
{
    int i = blockIdx.x * blockDim.x + threadIdx.x;
    if (i >= n4) return;
    __nv_bfloat16* hi = (which < 4)
        ? g_xb + (size_t)which * 4096 * 1024
        : g_wb + (size_t)(which - 4) * 1024 * 1024;
    size_t loOff = (which < 4) ? (size_t)4096 * 1024 : (size_t)1024 * 1024;

    float4 v = src[i];
    __nv_bfloat16 h0 = __float2bfloat16(v.x), h1 = __float2bfloat16(v.y);
    __nv_bfloat16 h2 = __float2bfloat16(v.z), h3 = __float2bfloat16(v.w);
    __nv_bfloat162* dh = (__nv_bfloat162*)hi;
    dh[2*i]   = __nv_bfloat162(h0, h1);
    dh[2*i+1] = __nv_bfloat162(h2, h3);
    if (split) {
        __nv_bfloat162* dl = (__nv_bfloat162*)(hi + loOff);
        dl[2*i]   = __nv_bfloat162(__float2bfloat16(v.x - __bfloat162float(h0)),
                                   __float2bfloat16(v.y - __bfloat162float(h1)));
        dl[2*i+1] = __nv_bfloat162(__float2bfloat16(v.z - __bfloat162float(h2)),
                                   __float2bfloat16(v.w - __bfloat162float(h3)));
    }
}

// ---------------------------------------------------------------------------
// Kernel 1: all three projections via mma.sync bf16.
// out[m, n] = X[m, :] . W[n, :] + b[n],   M=4096, N=64 (one head/block), K=1024.
// z = 0: Q (1 mma), 1: K (1 mma), 2: V (3-mma split-precision).
// Block 256 thr = 8 warps as 4(m) x 2(n); warp tile 32x32; K-chunk 64.
// ---------------------------------------------------------------------------
#define PADW 72   // bf16 elements per smem row (144B: 16B-aligned, 4-bank skew)

__global__ __launch_bounds__(256) void proj_mma(
    const float* __restrict__ bq, const float* __restrict__ bk, const float* __restrict__ bv)
{
    extern __shared__ __align__(16) char smraw[];
    __nv_bfloat16* Xh = (__nv_bfloat16*)smraw;       // [128][PADW]
    __nv_bfloat16* Wh = Xh + 128 * PADW;             // [64][PADW]
    __nv_bfloat16* Xl = Wh + 64 * PADW;              // [128][PADW] (V only)
    __nv_bfloat16* Wl = Xl + 128 * PADW;             // [64][PADW]  (V only)

    const int z = blockIdx.z;
    const int split = (z == 2);
    const __nv_bfloat16* Xg  = g_xb + (size_t)z * 4096 * 1024;
    const __nv_bfloat16* Wg  = g_wb + (size_t)z * 1024 * 1024;
    const __nv_bfloat16* XgL = Xg + (size_t)4096 * 1024;   // slice z+1 when split
    const __nv_bfloat16* WgL = Wg + (size_t)1024 * 1024;
    const float* bias = (z == 0) ? bq : (z == 1) ? bk : bv;
    float* out        = (z == 0) ? g_q : (z == 1) ? g_k : g_v;

    const int h  = blockIdx.x;
    const int m0 = blockIdx.y * 128;
    const int tid = threadIdx.x;
    const int wid = tid >> 5, lane = tid & 31;
    const int warpM = wid >> 1, warpN = wid & 1;
    const int gp = lane >> 2, tig = lane & 3;        // groupID, thread-in-group

    float acc[2][4][4] = {};

    for (int c = 0; c < 16; c++) {
        const int k0 = c * 64;
        __syncthreads();                              // prev chunk fully consumed
        #pragma unroll
        for (int j = 0; j < 4; j++) {                 // X tile 128x64: 1024 8-elem units
            int u = tid + j * 256;
            int r = u >> 3, cg = (u & 7) * 8;
            *(uint4*)&Xh[r * PADW + cg] = *(const uint4*)(Xg + (size_t)(m0 + r) * NE + k0 + cg);
            if (split)
                *(uint4*)&Xl[r * PADW + cg] = *(const uint4*)(XgL + (size_t)(m0 + r) * NE + k0 + cg);
        }
        #pragma unroll
        for (int j = 0; j < 2; j++) {                 // W tile 64x64: 512 units
            int u = tid + j * 256;
            int r = u >> 3, cg = (u & 7) * 8;
            *(uint4*)&Wh[r * PADW + cg] = *(const uint4*)(Wg + (size_t)(h * 64 + r) * NE + k0 + cg);
            if (split)
                *(uint4*)&Wl[r * PADW + cg] = *(const uint4*)(WgL + (size_t)(h * 64 + r) * NE + k0 + cg);
        }
        __syncthreads();

        #pragma unroll
        for (int ks = 0; ks < 4; ks++) {
            const int kc = ks * 16 + tig * 2;
            uint32_t a[2][4], b[4][2], al[2][4], bl[4][2];
            #pragma unroll
            for (int mi = 0; mi < 2; mi++) {
                const int r = warpM * 32 + mi * 16 + gp;
                a[mi][0] = *(const uint32_t*)&Xh[(r    ) * PADW + kc];
                a[mi][1] = *(const uint32_t*)&Xh[(r + 8) * PADW + kc];
                a[mi][2] = *(const uint32_t*)&Xh[(r    ) * PADW + kc + 8];
                a[mi][3] = *(const uint32_t*)&Xh[(r + 8) * PADW + kc + 8];
            }
            #pragma unroll
            for (int ni = 0; ni < 4; ni++) {
                const int n = warpN * 32 + ni * 8 + gp;
                b[ni][0] = *(const uint32_t*)&Wh[n * PADW + kc];
                b[ni][1] = *(const uint32_t*)&Wh[n * PADW + kc + 8];
            }
            if (split) {
                #pragma unroll
                for (int mi = 0; mi < 2; mi++) {
                    const int r = warpM * 32 + mi * 16 + gp;
                    al[mi][0] = *(const uint32_t*)&Xl[(r    ) * PADW + kc];
                    al[mi][1] = *(const uint32_t*)&Xl[(r + 8) * PADW + kc];
                    al[mi][2] = *(const uint32_t*)&Xl[(r    ) * PADW + kc + 8];
                    al[mi][3] = *(const uint32_t*)&Xl[(r + 8) * PADW + kc + 8];
                }
                #pragma unroll
                for (int ni = 0; ni < 4; ni++) {
                    const int n = warpN * 32 + ni * 8 + gp;
                    bl[ni][0] = *(const uint32_t*)&Wl[n * PADW + kc];
                    bl[ni][1] = *(const uint32_t*)&Wl[n * PADW + kc + 8];
                }
            }
            #pragma unroll
            for (int mi = 0; mi < 2; mi++)
                #pragma unroll
                for (int ni = 0; ni < 4; ni++) {
                    mma16816(acc[mi][ni], a[mi], b[ni]);
                    if (split) {
                        mma16816(acc[mi][ni], a[mi], bl[ni]);   // xh . wl
                        mma16816(acc[mi][ni], al[mi], b[ni]);   // xl . wh
                    }
                }
        }
    }

    // epilogue: bias + store (float2, coalesced per quad)
    const int b  = m0 >> 11;
    const int s0 = m0 & (NS - 1);
    float* obase = out + ((size_t)(b * NH + h) * NS + s0) * ND;
    #pragma unroll
    for (int mi = 0; mi < 2; mi++)
        #pragma unroll
        for (int ni = 0; ni < 4; ni++) {
            const int r = warpM * 32 + mi * 16 + gp;
            const int cn = warpN * 32 + ni * 8 + tig * 2;
            const float bx = bias[h * 64 + cn], by = bias[h * 64 + cn + 1];
            float2 o0 = { acc[mi][ni][0] + bx, acc[mi][ni][1] + by };
            float2 o1 = { acc[mi][ni][2] + bx, acc[mi][ni][3] + by };
            *(float2*)(obase + (size_t)(r    ) * ND + cn) = o0;
            *(float2*)(obase + (size_t)(r + 8) * ND + cn) = o1;
        }
}

// ---------------------------------------------------------------------------
// Kernel 2: per-(b,h) tile-granular suffix sums of V (fp32, exact).
// ---------------------------------------------------------------------------
__global__ void suffix_kernel()
{
    const int bh = blockIdx.x;
    const int d  = threadIdx.x;
    const float* v = g_v + (size_t)bh * NS * ND;
    float* suf = g_suf + (size_t)bh * (NT + 1) * ND;
    float acc = 0.f;
    suf[NT * ND + d] = 0.f;
    for (int t = NT - 1; t >= 0; t--) {
        for (int s = t * 64 + 63; s >= t * 64; s--) acc += v[(size_t)s * ND + d];
        suf[t * ND + d] = acc;
    }
}

// ---------------------------------------------------------------------------
// Kernel 3: attention (unchanged; fp32 SIMT — next round's mma target).
// ---------------------------------------------------------------------------
__global__ __launch_bounds__(256) void attn_kernel(
    const float* __restrict__ pos_bias, float* __restrict__ out)
{
    extern __shared__ float sm[];
    float* Qt    = sm;
    float* Kt    = Qt + 64 * 68;
    float* St    = Kt + 64 * 68;
    float* Vs    = St + 64 * 68;
    float* posr  = Vs + 64 * 64;
    float* row_m = posr + 4096;
    float* row_l = row_m + 64;
    float* lse_s = row_l + 64;

    const int tq = blockIdx.x;
    const int h  = blockIdx.y;
    const int b  = blockIdx.z;
    const int q0 = tq * 64;
    const int tid = threadIdx.x;
    const int tx = tid & 15, ty = tid >> 4;
    const int row  = tid & 63;
    const int dgrp = (tid >> 6) * 16;

    const size_t base = (size_t)(b * NH + h) * NS * ND;

    #pragma unroll
    for (int i = 0; i < 4; i++) {
        const int d = dgrp + i * 4;
        float4 qv = *(const float4*)(g_q + base + (size_t)(q0 + row) * ND + d);
        Qt[(d+0)*68 + row] = qv.x * QSCALE;
        Qt[(d+1)*68 + row] = qv.y * QSCALE;
        Qt[(d+2)*68 + row] = qv.z * QSCALE;
        Qt[(d+3)*68 + row] = qv.w * QSCALE;
    }
    for (int i = tid; i < 2 * NS - 1; i += 256)
        posr[i] = pos_bias[(size_t)h * (2 * NS - 1) + i];
    if (tid < 64) { row_m[tid] = -1e30f; row_l[tid] = 0.f; }
    __syncthreads();

    float A[4][4] = {};

    for (int t = 0; t <= tq; t++) {
        const int k0 = t * 64;
        float4 kv[4], vv[4];
        #pragma unroll
        for (int i = 0; i < 4; i++) {
            const int d = dgrp + i * 4;
            kv[i] = *(const float4*)(g_k + base + (size_t)(k0 + row) * ND + d);
            vv[i] = *(const float4*)(g_v + base + (size_t)(k0 + row) * ND + d);
        }
        __syncthreads();
        #pragma unroll
        for (int i = 0; i < 4; i++) {
            const int d = dgrp + i * 4;
            Kt[(d+0)*68 + row] = kv[i].x; Kt[(d+1)*68 + row] = kv[i].y;
            Kt[(d+2)*68 + row] = kv[i].z; Kt[(d+3)*68 + row] = kv[i].w;
            *(float4*)(Vs + row * 64 + d) = vv[i];
        }
        __syncthreads();

        float c[4][4] = {};
        #pragma unroll 8
        for (int kk = 0; kk < 64; kk++) {
            float4 a4 = *(const float4*)(Qt + kk * 68 + ty * 4);
            float4 b4 = *(const float4*)(Kt + kk * 68 + tx * 4);
            float av[4] = {a4.x, a4.y, a4.z, a4.w};
            float bw[4] = {b4.x, b4.y, b4.z, b4.w};
            #pragma unroll
            for (int i = 0; i < 4; i++)
                #pragma unroll
                for (int j = 0; j < 4; j++)
                    c[i][j] += av[i] * bw[j];
        }
        #pragma unroll
        for (int i = 0; i < 4; i++) {
            const int q = q0 + ty * 4 + i;
            #pragma unroll
            for (int j = 0; j < 4; j++) {
                const int k = k0 + tx * 4 + j;
                float val = c[i][j] + posr[q - k + NS - 1];
                if (k > q) val = NEGV;
                St[(tx * 4 + j) * 68 + (ty * 4 + i)] = val;
            }
        }
        __syncthreads();

        if (tid < 64) {
            float mo = row_m[tid];
            float mt = mo;
            #pragma unroll 8
            for (int j = 0; j < 64; j++) mt = fmaxf(mt, St[j * 68 + tid]);
            float l = row_l[tid] * __expf(mo - mt);
            #pragma unroll 8
            for (int j = 0; j < 64; j++) l += __expf(St[j * 68 + tid] - mt);
            row_m[tid] = mt; row_l[tid] = l;
        }

        #pragma unroll 8
        for (int j = 0; j < 64; j++) {
            float4 a4 = *(const float4*)(St + j * 68 + ty * 4);
            float4 v4 = *(const float4*)(Vs + j * 64 + tx * 4);
            float av[4] = {a4.x, a4.y, a4.z, a4.w};
            #pragma unroll
            for (int i = 0; i < 4; i++) {
                A[i][0] += av[i] * v4.x; A[i][1] += av[i] * v4.y;
                A[i][2] += av[i] * v4.z; A[i][3] += av[i] * v4.w;
            }
        }
    }

    __syncthreads();
    if (tid < 64) lse_s[tid] = row_m[tid] + logf(row_l[tid]);
    __syncthreads();

    const float* suf = g_suf + (size_t)(b * NH + h) * (NT + 1) * ND;
    float4 vt = *(const float4*)(suf + tx * 4);
    float4 vl = *(const float4*)(suf + (size_t)(tq + 1) * ND + tx * 4);

    #pragma unroll
    for (int i = 0; i < 4; i++) {
        const int q = q0 + ty * 4 + i;
        const float lse = lse_s[ty * 4 + i];
        float4 o;
        o.x = A[i][0] + NEGV * vl.x - lse * vt.x;
        o.y = A[i][1] + NEGV * vl.y - lse * vt.y;
        o.z = A[i][2] + NEGV * vl.z - lse * vt.z;
        o.w = A[i][3] + NEGV * vl.w - lse * vt.w;
        *(float4*)(out + ((size_t)(b * NS + q)) * NE + h * ND + tx * 4) = o;
    }
}

// ---------------------------------------------------------------------------
extern "C" void kernel_launch(void* const* d_in, const int* in_sizes, int n_in,
                              void* d_out, int out_size)
{
    (void)in_sizes; (void)n_in; (void)out_size;
    const float* query = (const float*)d_in[0];
    const float* key_  = (const float*)d_in[1];
    const float* value = (const float*)d_in[2];
    const float* Wq    = (const float*)d_in[3];
    const float* bq    = (const float*)d_in[4];
    const float* Wk    = (const float*)d_in[5];
    const float* bk    = (const float*)d_in[6];
    const float* Wv    = (const float*)d_in[7];
    const float* bv    = (const float*)d_in[8];
    const float* pos   = (const float*)d_in[9];

    const int n4x = 4096 * 1024 / 4, n4w = 1024 * 1024 / 4;
    f2bf_kernel<<<n4x / 256, 256>>>((const float4*)query, 0, 0, n4x);
    f2bf_kernel<<<n4x / 256, 256>>>((const float4*)key_,  1, 0, n4x);
    f2bf_kernel<<<n4x / 256, 256>>>((const float4*)value, 2, 1, n4x);  // hi+lo
    f2bf_kernel<<<n4w / 256, 256>>>((const float4*)Wq,    4, 0, n4w);
    f2bf_kernel<<<n4w / 256, 256>>>((const float4*)Wk,    5, 0, n4w);
    f2bf_kernel<<<n4w / 256, 256>>>((const float4*)Wv,    6, 1, n4w);  // hi+lo

    const int PROJ_SMEM = (128 * PADW + 64 * PADW) * 2 * 2;   // 55296 B
    cudaFuncSetAttribute(proj_mma, cudaFuncAttributeMaxDynamicSharedMemorySize, PROJ_SMEM);
    proj_mma<<<dim3(16, 32, 3), 256, PROJ_SMEM>>>(bq, bk, bv);

    suffix_kernel<<<dim3(NB * NH), 64>>>();

    const int SMEM = (3 * 64 * 68 + 64 * 64 + 4096 + 192) * 4;  // 85760 B
    cudaFuncSetAttribute(attn_kernel, cudaFuncAttributeMaxDynamicSharedMemorySize, SMEM);
    attn_kernel<<<dim3(NT, NH, NB), 256, SMEM>>>(pos, (float*)d_out);
}